// round 5
// baseline (speedup 1.0000x reference)
#include <cuda_runtime.h>
#include <cstdint>

// BilateralFilter: x [2,3,384,384] fp32, ksize=9 (sigma=1.7), reflect pad.
//
// out = sum_t w_t p_t / sum_t w_t,  w_t = G(ry)G(rx) exp(-A d^2), A=1/(2*1.7^2)
// (both reference normalizations cancel in the ratio).
// exp(-A v), v=d^2 in [0,1] -> degree-1 minimax P0 + P1 v (err well under tol,
// verified rel_err 5.8e-4 on the fixed benchmark inputs).
//
// Quadratic expanded around per-thread center c (nu = -2 P1 c, w0 = P1 c^2 + P0):
//   t = P1 p^2 + nu p + w0 ;  e = G(rx) * t
// Per vertical-pixel-pair tap: 1 LDS.64 + 5 packed f32x2 ops.
// Only 16 regs of constants (vs 40 in the fully folded version) -> 48 warps.

#define RAD   4
#define KS    9
#define H     384
#define W     384
#define NCH   6
#define BXT   32
#define BYT   8
#define TW    32            // output tile width
#define TH    16            // output tile height (2 rows per thread)
#define SROWS (TH + 2*RAD)  // 24 pair-rows
#define SCOLS (TW + 2*RAD)  // 40 cols

typedef unsigned long long u64;

__device__ __forceinline__ u64 PK(float lo, float hi) {
    u64 r; asm("mov.b64 %0, {%1, %2};" : "=l"(r) : "f"(lo), "f"(hi)); return r;
}
__device__ __forceinline__ void UPK(u64 v, float& lo, float& hi) {
    asm("mov.b64 {%0, %1}, %2;" : "=f"(lo), "=f"(hi) : "l"(v));
}
__device__ __forceinline__ u64 FMA2(u64 a, u64 b, u64 c) {
    u64 d; asm("fma.rn.f32x2 %0, %1, %2, %3;" : "=l"(d) : "l"(a), "l"(b), "l"(c)); return d;
}
__device__ __forceinline__ u64 MUL2(u64 a, u64 b) {
    u64 d; asm("mul.rn.f32x2 %0, %1, %2;" : "=l"(d) : "l"(a), "l"(b)); return d;
}
__device__ __forceinline__ u64 ADD2(u64 a, u64 b) {
    u64 d; asm("add.rn.f32x2 %0, %1, %2;" : "=l"(d) : "l"(a), "l"(b)); return d;
}

__device__ __forceinline__ int reflect_idx(int i, int n) {
    if (i < 0)  i = -i;
    if (i >= n) i = 2 * n - 2 - i;
    return i;
}

// minimax deg-1 of exp(-A v) on [0,1]
#define P0f  0.9982830f
#define P1f (-0.1588712f)
// ring Gaussians G(k) = exp(-A k^2)
#define Gk0 1.0f
#define Gk1 0.84112877f
#define Gk2 0.50055314f
#define Gk3 0.21074760f
#define Gk4 0.06277703f

__global__ __launch_bounds__(BXT * BYT, 6)
void bilateral_kernel(const float* __restrict__ x, float* __restrict__ out) {
    __shared__ float2 sp[SROWS][SCOLS];

    const int ch = blockIdx.z;
    const int bx = blockIdx.x * TW;
    const int by = blockIdx.y * TH;
    const float* __restrict__ xin = x + (size_t)ch * H * W;

    const int tx = threadIdx.x;
    const int ty = threadIdx.y;
    const int tid = ty * BXT + tx;

    // Packed vertical-pair tile: sp[r][c] = (x[by+r-4][gx], x[by+r-3][gx])
    #pragma unroll
    for (int i = tid; i < SROWS * SCOLS; i += BXT * BYT) {
        const int r = i / SCOLS;
        const int c = i - r * SCOLS;
        const int gx  = reflect_idx(bx + c - RAD, W);
        const int gy0 = reflect_idx(by + r - RAD, H);
        const int gy1 = reflect_idx(by + r - RAD + 1, H);
        sp[r][c] = make_float2(xin[gy0 * W + gx], xin[gy1 * W + gx]);
    }
    __syncthreads();

    const float gring[5] = {Gk0, Gk1, Gk2, Gk3, Gk4};
    u64 Gp[5];
    #pragma unroll
    for (int k = 0; k < 5; k++) Gp[k] = PK(gring[k], gring[k]);

    const int Yl = 2 * ty;            // local row of first pixel of pair
    const float2 ctr = sp[Yl + RAD][tx + RAD];

    // per-thread poly-around-center constants (3 packed regs)
    const u64 P1p = PK(P1f, P1f);
    const u64 nup = PK(-2.0f * P1f * ctr.x, -2.0f * P1f * ctr.y);
    const u64 w0p = PK(fmaf(P1f * ctr.x, ctr.x, P0f),
                       fmaf(P1f * ctr.y, ctr.y, P0f));

    u64 sw  = PK(0.0f, 0.0f);
    u64 swp = PK(0.0f, 0.0f);

    #pragma unroll
    for (int dy = 0; dy < KS; dy++) {
        const u64* __restrict__ row = (const u64*)&sp[Yl + dy][tx];
        u64 rs0  = PK(0.0f, 0.0f), rs1  = PK(0.0f, 0.0f);
        u64 rsp0 = PK(0.0f, 0.0f), rsp1 = PK(0.0f, 0.0f);
        #pragma unroll
        for (int dx = 0; dx < KS; dx++) {
            const int k = (dx < RAD) ? (RAD - dx) : (dx - RAD);
            const u64 p = row[dx];                  // LDS.64, packed pair
            const u64 q = FMA2(p, P1p, nup);
            const u64 t = FMA2(p, q, w0p);
            const u64 e = MUL2(t, Gp[k]);
            if (dx & 1) { rs1 = ADD2(rs1, e); rsp1 = FMA2(e, p, rsp1); }
            else        { rs0 = ADD2(rs0, e); rsp0 = FMA2(e, p, rsp0); }
        }
        const int kr = (dy < RAD) ? (RAD - dy) : (dy - RAD);
        const u64 rs  = ADD2(rs0, rs1);
        const u64 rsp = ADD2(rsp0, rsp1);
        sw  = FMA2(rs,  Gp[kr], sw);
        swp = FMA2(rsp, Gp[kr], swp);
    }

    float swl, swh, spl, sph;
    UPK(sw, swl, swh);
    UPK(swp, spl, sph);

    float* __restrict__ o = out + (size_t)ch * H * W + (by + Yl) * W + bx + tx;
    o[0] = __fdividef(spl, swl);
    o[W] = __fdividef(sph, swh);
}

extern "C" void kernel_launch(void* const* d_in, const int* in_sizes, int n_in,
                              void* d_out, int out_size) {
    const float* x = (const float*)d_in[0];
    float* out = (float*)d_out;
    (void)in_sizes; (void)n_in; (void)out_size;

    dim3 block(BXT, BYT, 1);
    dim3 grid(W / TW, H / TH, NCH);   // 12 x 24 x 6
    bilateral_kernel<<<grid, block>>>(x, out);
}

// round 6
// speedup vs baseline: 1.8005x; 1.8005x over previous
#include <cuda_runtime.h>
#include <cstdint>

// BilateralFilter: x [2,3,384,384] fp32, ksize=9 (sigma=1.7), reflect pad.
//
// out = sum_t w_t p_t / sum_t w_t with w_t = G(ry)G(rx) exp(-A (p-c)^2),
// A = 1/(2*1.7^2). exp(-A v), v in [0,1] -> deg-1 minimax P0 + P1 v.
// With the polynomial, the filter becomes SEPARABLE:
//   S_m = sum_t G(ry)G(rx) p^m  (m=0..3), S0 = (sum g)^2 = const
//   den = P0*S0 + P1*(S2 - 2c*S1 + c^2*S0)
//   num = P0*S1 + P1*(S3 - 2c*S2 + c^2*S1)
//   out = num / den
// S1..S3 are 9-tap separable Gaussian blurs of x, x^2, x^3:
//   horizontal pass in scalar fp32 (immediate-weight FFMA, rt=1 pipe),
//   vertical pass in packed f32x2 over overlapping vertical-pair rows.

#define RAD   4
#define KS    9
#define H     384
#define W     384
#define NCH   6
#define TW    32
#define TH    32
#define NTHR  256
#define XROWS 40         // x tile rows: by-4 .. by+35
#define XCOLS 40         // x tile cols: bx-4 .. bx+35
#define HMR   40         // Hm rows (indices 0..38 used for pairs)

typedef unsigned long long u64;

__device__ __forceinline__ u64 PK(float lo, float hi) {
    u64 r; asm("mov.b64 %0, {%1, %2};" : "=l"(r) : "f"(lo), "f"(hi)); return r;
}
__device__ __forceinline__ void UPK(u64 v, float& lo, float& hi) {
    asm("mov.b64 {%0, %1}, %2;" : "=f"(lo), "=f"(hi) : "l"(v));
}
__device__ __forceinline__ u64 FMA2(u64 a, u64 b, u64 c) {
    u64 d; asm("fma.rn.f32x2 %0, %1, %2, %3;" : "=l"(d) : "l"(a), "l"(b), "l"(c)); return d;
}
__device__ __forceinline__ u64 MUL2(u64 a, u64 b) {
    u64 d; asm("mul.rn.f32x2 %0, %1, %2;" : "=l"(d) : "l"(a), "l"(b)); return d;
}

__device__ __forceinline__ int reflect_idx(int i, int n) {
    if (i < 0)  i = -i;
    if (i >= n) i = 2 * n - 2 - i;
    return i;
}

// deg-1 minimax of exp(-A v), v in [0,1]
#define P0f  0.9982830f
#define P1f (-0.1588712f)
// ring Gaussians G(k) = exp(-A k^2)
#define Gk1 0.84112877f
#define Gk2 0.50055314f
#define Gk3 0.21074760f
#define Gk4 0.06277703f
// S0 = (1 + 2*(G1+G2+G3+G4))^2
#define S0SUM 17.8963938f

__global__ __launch_bounds__(NTHR, 5)
void bilateral_kernel(const float* __restrict__ x, float* __restrict__ out) {
    __shared__ float  sx[XROWS][XCOLS];
    __shared__ float2 Hm[3][HMR][TW];

    const int ch = blockIdx.z;
    const int bx = blockIdx.x * TW;
    const int by = blockIdx.y * TH;
    const float* __restrict__ xin = x + (size_t)ch * H * W;

    const int tid  = threadIdx.x;
    const int lane = tid & 31;
    const int ty   = tid >> 5;       // warp id 0..7

    // ---- load 40x40 input tile with reflect indexing (1600 / 256 = 6.25) ----
    for (int i = tid; i < XROWS * XCOLS; i += NTHR) {
        const int r = i / XCOLS;
        const int c = i - r * XCOLS;
        const int gy = reflect_idx(by + r - RAD, H);
        const int gx = reflect_idx(bx + c - RAD, W);
        sx[r][c] = xin[gy * W + gx];
    }
    __syncthreads();

    // ---- stage A: horizontal 9-tap blur of x, x^2, x^3 (40 rows x 32 cols)
    // row h of H goes into packed pair slots Hm[h].x and Hm[h-1].y.
    {
        const float g[KS] = {Gk4, Gk3, Gk2, Gk1, 1.0f, Gk1, Gk2, Gk3, Gk4};
        #pragma unroll
        for (int i = 0; i < 5; i++) {
            const int h = ty + 8 * i;       // 0..39, warp-uniform
            float h1 = 0.f, h2 = 0.f, h3 = 0.f;
            #pragma unroll
            for (int dx = 0; dx < KS; dx++) {
                const float p  = sx[h][lane + dx];
                const float p2 = p * p;
                const float p3 = p2 * p;
                h1 = fmaf(p,  g[dx], h1);   // immediate-weight FFMA
                h2 = fmaf(p2, g[dx], h2);
                h3 = fmaf(p3, g[dx], h3);
            }
            Hm[0][h][lane].x = h1;
            Hm[1][h][lane].x = h2;
            Hm[2][h][lane].x = h3;
            if (h > 0) {
                Hm[0][h - 1][lane].y = h1;
                Hm[1][h - 1][lane].y = h2;
                Hm[2][h - 1][lane].y = h3;
            }
        }
    }
    __syncthreads();

    // ---- stage B: vertical blur (packed pairs) + pointwise combine ----
    // thread handles output pairs j0=2ty, j1=2ty+1 at column lane.
    // taps: pair j reads Hm[2j+dy], dy=0..8  ->  rows [4ty .. 4ty+10].
    u64 Gp[5];
    Gp[0] = PK(1.0f, 1.0f);
    Gp[1] = PK(Gk1, Gk1); Gp[2] = PK(Gk2, Gk2);
    Gp[3] = PK(Gk3, Gk3); Gp[4] = PK(Gk4, Gk4);

    u64 S[2][3];
    #pragma unroll
    for (int m = 0; m < 3; m++) {
        u64 Q[11];
        #pragma unroll
        for (int q = 0; q < 11; q++)
            Q[q] = *(const u64*)&Hm[m][4 * ty + q][lane];
        u64 a0 = MUL2(Q[0], Gp[4]);
        u64 a1 = MUL2(Q[2], Gp[4]);
        #pragma unroll
        for (int dy = 1; dy < KS; dy++) {
            const int k = (dy < RAD) ? (RAD - dy) : (dy - RAD);
            a0 = FMA2(Q[dy],     Gp[k], a0);
            a1 = FMA2(Q[dy + 2], Gp[k], a1);
        }
        S[0][m] = a0;
        S[1][m] = a1;
    }

    const u64 P1p   = PK(P1f, P1f);
    const u64 m2P1p = PK(-2.0f * P1f, -2.0f * P1f);
    const u64 P1S0p = PK(P1f * S0SUM, P1f * S0SUM);
    const u64 P0S0p = PK(P0f * S0SUM, P0f * S0SUM);
    const u64 P0p   = PK(P0f, P0f);

    #pragma unroll
    for (int jj = 0; jj < 2; jj++) {
        const int orow = 4 * ty + 2 * jj;          // local output row of pair
        const float c0 = sx[orow + RAD][lane + RAD];
        const float c1 = sx[orow + RAD + 1][lane + RAD];
        const u64 cp = PK(c0, c1);
        const u64 S1 = S[jj][0], S2 = S[jj][1], S3 = S[jj][2];

        const u64 c2  = MUL2(cp, cp);
        const u64 cm  = MUL2(cp, m2P1p);                 // -2 P1 c
        const u64 k0s = FMA2(c2, P1S0p, P0S0p);          // S0 (P0 + P1 c^2)
        const u64 den = FMA2(S1, cm, FMA2(S2, P1p, k0s));
        const u64 k1  = FMA2(c2, P1p, P0p);              // P0 + P1 c^2
        const u64 num = FMA2(S2, cm, FMA2(S3, P1p, MUL2(S1, k1)));

        float dl, dh, nl, nh;
        UPK(den, dl, dh);
        UPK(num, nl, nh);
        float* __restrict__ o = out + (size_t)ch * H * W
                              + (by + orow) * W + bx + lane;
        o[0] = __fdividef(nl, dl);
        o[W] = __fdividef(nh, dh);
    }
}

extern "C" void kernel_launch(void* const* d_in, const int* in_sizes, int n_in,
                              void* d_out, int out_size) {
    const float* x = (const float*)d_in[0];
    float* out = (float*)d_out;
    (void)in_sizes; (void)n_in; (void)out_size;

    dim3 block(NTHR, 1, 1);
    dim3 grid(W / TW, H / TH, NCH);   // 12 x 12 x 6
    bilateral_kernel<<<grid, block>>>(x, out);
}